// round 14
// baseline (speedup 1.0000x reference)
#include <cuda_runtime.h>

#define NN 200000
#define EE 400000
#define DD 64
#define BBATCH 16
#define NLVL 12
#define SCAN_NB ((NN + 1023) / 1024)   // 196 (degree scans, 1024/block)
#define NB2 784                        // node-chunk blocks (256 nodes/block)
#define PGRID 296
#define SLOT_MASK 0xFFFFF
#define FOUT_FLAG 0x40000000
#define PFK 8                          // prefetched edges per row

// ---------------- device scratch ----------------
__device__ float g_fout[NN * DD];       // slot-indexed forward outputs
__device__ float g_bout[NN * DD];       // slot-indexed backward outputs
__device__ float g_tab[9 * DD];         // 9 distinct f0 rows (nt*3+nip)
__device__ int g_indeg[NN], g_outdeg[NN];
__device__ int g_fslot[NN], g_bslot[NN];     // node -> slot (fslot packs type<<20)
__device__ int g_fdeg[NN], g_bdeg[NN];       // slot-indexed degree
__device__ int g_feptr[NN + 1], g_beptr[NN + 1];
__device__ int g_fcur_e[NN], g_bcur_e[NN];
__device__ int g_fsrc[EE];              // fwd edges by dst-slot: packed fslot[src]
__device__ int2 g_bedge[EE];            // bwd edges by src-slot: (bslot[dst], fidx[dst])
__device__ int g_foff[NLVL + 1], g_boff[NLVL + 1];
__device__ int g_lhist[2 * NLVL * NB2];
__device__ int g_bsum[2][SCAN_NB], g_bsum_s[2][SCAN_NB];
// grid barrier (generation counter survives graph replays)
__device__ unsigned g_cnt = 0;
__device__ volatile unsigned g_gen = 0;   // volatile: spin loop must not be elided

__device__ __forceinline__ unsigned enc_f(float f) {
    unsigned u = __float_as_uint(f);
    return (u & 0x80000000u) ? ~u : (u | 0x80000000u);
}
__device__ __forceinline__ float dec_f(unsigned u) {
    return (u & 0x80000000u) ? __uint_as_float(u & 0x7FFFFFFFu)
                             : __uint_as_float(~u);
}
#define NEGMAX (-3.402823466e38f)

// ---------------- K0: zero degree arrays + init output buffer ----------------
__global__ void k_zero(float* __restrict__ out) {
    int stride = gridDim.x * blockDim.x;
    for (int i = blockIdx.x * blockDim.x + threadIdx.x; i < NN; i += stride) {
        g_indeg[i] = 0;
        g_outdeg[i] = 0;
        if (i < BBATCH * 2 * DD) {
            int col = i & 127;
            ((unsigned*)out)[i] = (col < 64) ? 0x00800000u : 0u;
        }
    }
}

// ---------------- K1: node level hists (pre-sync) + edge degrees (post-sync) ----------------
__global__ void k_deg_hist(const int* __restrict__ ei, const int* __restrict__ fl,
                           const int* __restrict__ bl) {
    __shared__ int sh[2 * NLVL];
    int t = threadIdx.x;
    if (t < 2 * NLVL) sh[t] = 0;
    __syncthreads();
    int idx = blockIdx.x * 256 + t;          // one node per thread
    if (idx < NN) {
        atomicAdd(&sh[fl[idx]], 1);
        atomicAdd(&sh[NLVL + bl[idx]], 1);
    }
    cudaGridDependencySynchronize();         // wait k_zero (g_indeg/outdeg ready)
    int stride = gridDim.x * blockDim.x;
    for (int i = blockIdx.x * blockDim.x + t; i < EE; i += stride) {
        atomicAdd(&g_indeg[ei[EE + i]], 1);
        atomicAdd(&g_outdeg[ei[i]], 1);
    }
    __syncthreads();
    if (t < 2 * NLVL) g_lhist[t * NB2 + blockIdx.x] = sh[t];
}

// ---------------- K2: scan block hists -> per-(blk,lvl) offsets + foff/boff ----------------
__global__ void k_hscan() {
    __shared__ int tot[2 * NLVL];
    __shared__ int off_s[2][NLVL + 1];
    int t = threadIdx.x;
    int wid = t >> 5, lane = t & 31;       // 24 warps
    cudaGridDependencySynchronize();
    int* row = g_lhist + wid * NB2;
    int carry = 0;
#pragma unroll
    for (int r = 0; r < (NB2 + 31) / 32; r++) {
        int idx = r * 32 + lane;
        int v = (idx < NB2) ? row[idx] : 0;
        int incl = v;
#pragma unroll
        for (int o = 1; o < 32; o <<= 1) {
            int n = __shfl_up_sync(0xffffffffu, incl, o);
            if (lane >= o) incl += n;
        }
        if (idx < NB2) row[idx] = incl - v + carry;
        carry += __shfl_sync(0xffffffffu, incl, 31);
    }
    if (lane == 0) tot[wid] = carry;
    __syncthreads();
    if (wid < 2) {
        int hv = (lane < NLVL) ? tot[wid * NLVL + lane] : 0;
        int v = hv;
#pragma unroll
        for (int o = 1; o < 32; o <<= 1) {
            int n = __shfl_up_sync(0xffffffffu, v, o);
            if (lane >= o) v += n;
        }
        int excl = v - hv;
        if (lane <= NLVL) {
            off_s[wid][lane] = excl;
            (wid ? g_boff : g_foff)[lane] = excl;
        }
    }
    __syncthreads();
    int add = off_s[wid / NLVL][wid % NLVL];
#pragma unroll
    for (int r = 0; r < (NB2 + 31) / 32; r++) {
        int idx = r * 32 + lane;
        if (idx < NB2) row[idx] += add;
    }
}

// ---------------- K3: assign slots (pack nt/nip type into fslot) ----------------
__global__ void k_assign2(const int* __restrict__ fl, const int* __restrict__ bl,
                          const int* __restrict__ nt, const int* __restrict__ nip) {
    __shared__ int sc[2 * NLVL];
    int t = threadIdx.x;
    int v = blockIdx.x * 256 + t;            // one node per thread
    int type = 0, flv = 0, blv = 0;
    if (v < NN) {
        type = nt[v] * 3 + nip[v];
        flv = fl[v];
        blv = bl[v];
    }
    cudaGridDependencySynchronize();
    if (t < 2 * NLVL) sc[t] = g_lhist[t * NB2 + blockIdx.x];
    __syncthreads();
    if (v < NN) {
        int s = atomicAdd(&sc[flv], 1);
        g_fslot[v] = s | (type << 20);
        g_fdeg[s] = g_indeg[v];
        int s2 = atomicAdd(&sc[NLVL + blv], 1);
        g_bslot[v] = s2;
        g_bdeg[s2] = g_outdeg[v];
    }
}

// ---------------- K4: block-local exclusive scans of slot degrees ----------------
__global__ void k_scan1() {
    int which = blockIdx.x / SCAN_NB;   // 0 = fdeg, 1 = bdeg
    int blk = blockIdx.x % SCAN_NB;
    const int* deg = which ? g_bdeg : g_fdeg;
    int* ptr = which ? g_beptr : g_feptr;
    __shared__ int sh[256];
    int base = blk * 1024 + threadIdx.x * 4;
    cudaGridDependencySynchronize();
    int v[4];
    int s = 0;
#pragma unroll
    for (int j = 0; j < 4; j++) {
        int idx = base + j;
        v[j] = (idx < NN) ? deg[idx] : 0;
        s += v[j];
    }
    sh[threadIdx.x] = s;
    __syncthreads();
    for (int off = 1; off < 256; off <<= 1) {
        int t = 0;
        if (threadIdx.x >= off) t = sh[threadIdx.x - off];
        __syncthreads();
        sh[threadIdx.x] += t;
        __syncthreads();
    }
    int run = sh[threadIdx.x] - s;
#pragma unroll
    for (int j = 0; j < 4; j++) {
        int idx = base + j;
        if (idx < NN) ptr[idx] = run;
        run += v[j];
    }
    if (threadIdx.x == 255) g_bsum[which][blk] = sh[255];
}

// ---------------- K5: build f0 table (pre-sync) + scan of block sums ----------------
__global__ void k_scan2p(const float* __restrict__ Wenc, const float* __restrict__ benc) {
    __shared__ int sh[256];
    int t = threadIdx.x;
    for (int i = t; i < 9 * DD; i += 256) {
        int ty = i >> 6, d = i & 63;
        g_tab[i] = (float)(ty / 3) * Wenc[d] + (float)(ty % 3) * Wenc[64 + d] + benc[d];
    }
    cudaGridDependencySynchronize();
#pragma unroll
    for (int w = 0; w < 2; w++) {
        int v = (t < SCAN_NB) ? g_bsum[w][t] : 0;
        sh[t] = v;
        __syncthreads();
        for (int off = 1; off < 256; off <<= 1) {
            int x = 0;
            if (t >= off) x = sh[t - off];
            __syncthreads();
            sh[t] += x;
            __syncthreads();
        }
        if (t < SCAN_NB) g_bsum_s[w][t] = sh[t] - v;
        __syncthreads();
    }
    if (t == 0) { g_feptr[NN] = EE; g_beptr[NN] = EE; }
}

// ---------------- K6: add block offsets, init edge-scatter cursors ----------------
__global__ void k_scan3() {
    int stride = gridDim.x * blockDim.x;
    cudaGridDependencySynchronize();
    for (int i = blockIdx.x * blockDim.x + threadIdx.x; i < 2 * NN; i += stride) {
        if (i < NN) {
            int v = g_feptr[i] + g_bsum_s[0][i >> 10];
            g_feptr[i] = v;
            g_fcur_e[i] = v;
        } else {
            int j = i - NN;
            int v = g_beptr[j] + g_bsum_s[1][j >> 10];
            g_beptr[j] = v;
            g_bcur_e[j] = v;
        }
    }
}

// ---------------- K7: scatter edges into slot-ordered lists ----------------
__global__ void k_scatter_e(const int* __restrict__ ei, const int* __restrict__ fl) {
    int stride = gridDim.x * blockDim.x;
    cudaGridDependencySynchronize();
    for (int i = blockIdx.x * blockDim.x + threadIdx.x; i < EE; i += stride) {
        int src = ei[i], dst = ei[EE + i];
        int fp_src = g_fslot[src];             // packed slot | type<<20
        int fp_dst = g_fslot[dst];
        int p = atomicAdd(&g_fcur_e[fp_dst & SLOT_MASK], 1);
        g_fsrc[p] = fp_src;
        int bs_src = g_bslot[src];
        int bs_dst = g_bslot[dst];
        int q = atomicAdd(&g_bcur_e[bs_src], 1);
        int fidx = fp_dst | ((fl[dst] >= 1) ? FOUT_FLAG : 0);
        g_bedge[q] = make_int2(bs_dst, fidx);
    }
}

// ---------------- grid-wide software barrier (volatile tight spin) ----------------
__device__ __forceinline__ void grid_bar(unsigned target) {
    __threadfence();
    __syncthreads();
    if (threadIdx.x == 0) {
        unsigned t = atomicAdd(&g_cnt, 1u);
        if (t == (unsigned)gridDim.x - 1u) {
            g_cnt = 0u;
            __threadfence();
            g_gen = target;
        } else {
            while (g_gen != target) { }   // volatile read each iteration
        }
        __threadfence();
    }
    __syncthreads();
}

__device__ __forceinline__ void pool_flush(int cb, float2 mx, float2 sm, int lane,
                                           float* out) {
    int d = 2 * lane;
    unsigned* uo = (unsigned*)out;
    atomicMax(&uo[cb * 128 + d], enc_f(mx.x));
    atomicMax(&uo[cb * 128 + d + 1], enc_f(mx.y));
    atomicAdd(&out[cb * 128 + 64 + d], sm.x);
    atomicAdd(&out[cb * 128 + 64 + d + 1], sm.y);
}

// ---------------- persistent: 22 fused levels + pool + fixup ----------------
__global__ void __launch_bounds__(256, 2) k_persist(
    const int* __restrict__ nt, const int* __restrict__ batch,
    const int* __restrict__ fl, const int* __restrict__ bl,
    const float* __restrict__ W_f, const float* __restrict__ b_f,
    const float* __restrict__ W_b, const float* __restrict__ b_b,
    float* __restrict__ out) {

    __shared__ float sW[64][64];
    __shared__ float sA[64][68];

    const int lane = threadIdx.x & 31;
    const int tx = threadIdx.x & 15, ty = threadIdx.x >> 4;
    const int n0 = tx << 2, m0 = ty << 2;
    const int r = threadIdx.x >> 2;
    const int c16 = (threadIdx.x & 3) << 4;

    // prefetch state: next phase's first-tile edge data (index data = prep output,
    // fully written before this kernel starts -> safe to read any time)
    int pf_e0 = 0, pf_e1 = 0;
    int pf_a[PFK], pf_b[PFK];
#pragma unroll
    for (int k = 0; k < PFK; k++) { pf_a[k] = 0; pf_b[k] = 0; }

    // pre-sync prologue: dir-0 weights are graph-constant inputs
    for (int i = threadIdx.x; i < 4096; i += 256) sW[i >> 6][i & 63] = W_f[i];

    cudaGridDependencySynchronize();

    unsigned base = 0, nbar = 0;
    if (threadIdx.x == 0) base = g_gen;

    // prefetch for first phase (dir 0, level 1)
    {
        int start = g_foff[1];
        int cnt = g_foff[2] - start;
        int m = (int)blockIdx.x * 64 + r;
        if (m < cnt) {
            int slot = start + m;
            pf_e0 = __ldg(g_feptr + slot);
            pf_e1 = __ldg(g_feptr + slot + 1);
            int dg = pf_e1 - pf_e0;
#pragma unroll
            for (int k = 0; k < PFK; k++)
                if (k < dg) pf_a[k] = __ldg(g_fsrc + pf_e0 + k);
        } else { pf_e0 = pf_e1 = 0; }
    }

    for (int dir = 0; dir < 2; dir++) {
        const float* bias = dir ? b_b : b_f;
        const int* off = dir ? g_boff : g_foff;
        const int* eptr = dir ? g_beptr : g_feptr;
        const int* deg = dir ? g_bdeg : g_fdeg;

        if (dir == 1) {
            for (int i = threadIdx.x; i < 4096; i += 256) sW[i >> 6][i & 63] = W_b[i];
        }
        float4 bs = *(const float4*)(bias + n0);
        int off1 = off[1];

        for (int l = 1; l < NLVL; l++) {
            int start = off[l];
            int cnt = off[l + 1] - start;
            int ntiles = (cnt + 63) >> 6;

            for (int tile = blockIdx.x; tile < ntiles; tile += gridDim.x) {
                int m = tile * 64 + r;
                float4 a0 = {0,0,0,0}, a1 = {0,0,0,0}, a2 = {0,0,0,0}, a3 = {0,0,0,0};
                if (m < cnt) {
                    bool upf = (tile == (int)blockIdx.x);
                    int slot = start + m;
                    int e0, e1;
                    if (upf) { e0 = pf_e0; e1 = pf_e1; }
                    else { e0 = __ldg(eptr + slot); e1 = __ldg(eptr + slot + 1); }
                    int dg = e1 - e0;
                    if (dir == 0) {
#pragma unroll
                        for (int k = 0; k < PFK; k++) {
                            if (k < dg) {
                                int v = upf ? pf_a[k] : __ldg(g_fsrc + e0 + k);
                                int s = v & SLOT_MASK;
                                const float* hb = (s >= off1 && s < start)
                                    ? g_fout + (size_t)s * DD
                                    : g_tab + ((v >> 20) & 0xF) * DD;
                                const float4* b = (const float4*)(hb + c16);
                                float4 v0 = b[0], v1 = b[1], v2 = b[2], v3 = b[3];
                                a0.x += v0.x; a0.y += v0.y; a0.z += v0.z; a0.w += v0.w;
                                a1.x += v1.x; a1.y += v1.y; a1.z += v1.z; a1.w += v1.w;
                                a2.x += v2.x; a2.y += v2.y; a2.z += v2.z; a2.w += v2.w;
                                a3.x += v3.x; a3.y += v3.y; a3.z += v3.z; a3.w += v3.w;
                            }
                        }
                        for (int e = e0 + PFK; e < e1; e++) {
                            int v = __ldg(g_fsrc + e);
                            int s = v & SLOT_MASK;
                            const float* hb = (s >= off1 && s < start)
                                ? g_fout + (size_t)s * DD
                                : g_tab + ((v >> 20) & 0xF) * DD;
                            const float4* b = (const float4*)(hb + c16);
                            float4 v0 = b[0], v1 = b[1], v2 = b[2], v3 = b[3];
                            a0.x += v0.x; a0.y += v0.y; a0.z += v0.z; a0.w += v0.w;
                            a1.x += v1.x; a1.y += v1.y; a1.z += v1.z; a1.w += v1.w;
                            a2.x += v2.x; a2.y += v2.y; a2.z += v2.z; a2.w += v2.w;
                            a3.x += v3.x; a3.y += v3.y; a3.z += v3.z; a3.w += v3.w;
                        }
                    } else {
#pragma unroll
                        for (int k = 0; k < PFK; k++) {
                            if (k < dg) {
                                int sx, fx;
                                if (upf) { sx = pf_a[k]; fx = pf_b[k]; }
                                else { int2 ee = __ldg(g_bedge + e0 + k); sx = ee.x; fx = ee.y; }
                                const float* hb;
                                if (sx >= off1 && sx < start) {
                                    hb = g_bout + (size_t)sx * DD;
                                } else {
                                    hb = (fx & FOUT_FLAG)
                                        ? g_fout + (size_t)(fx & SLOT_MASK) * DD
                                        : g_tab + ((fx >> 20) & 0xF) * DD;
                                }
                                const float4* b = (const float4*)(hb + c16);
                                float4 v0 = b[0], v1 = b[1], v2 = b[2], v3 = b[3];
                                a0.x += v0.x; a0.y += v0.y; a0.z += v0.z; a0.w += v0.w;
                                a1.x += v1.x; a1.y += v1.y; a1.z += v1.z; a1.w += v1.w;
                                a2.x += v2.x; a2.y += v2.y; a2.z += v2.z; a2.w += v2.w;
                                a3.x += v3.x; a3.y += v3.y; a3.z += v3.z; a3.w += v3.w;
                            }
                        }
                        for (int e = e0 + PFK; e < e1; e++) {
                            int2 ee = __ldg(g_bedge + e);
                            int sx = ee.x;
                            const float* hb;
                            if (sx >= off1 && sx < start) {
                                hb = g_bout + (size_t)sx * DD;
                            } else {
                                int fx = ee.y;
                                hb = (fx & FOUT_FLAG)
                                    ? g_fout + (size_t)(fx & SLOT_MASK) * DD
                                    : g_tab + ((fx >> 20) & 0xF) * DD;
                            }
                            const float4* b = (const float4*)(hb + c16);
                            float4 v0 = b[0], v1 = b[1], v2 = b[2], v3 = b[3];
                            a0.x += v0.x; a0.y += v0.y; a0.z += v0.z; a0.w += v0.w;
                            a1.x += v1.x; a1.y += v1.y; a1.z += v1.z; a1.w += v1.w;
                            a2.x += v2.x; a2.y += v2.y; a2.z += v2.z; a2.w += v2.w;
                            a3.x += v3.x; a3.y += v3.y; a3.z += v3.z; a3.w += v3.w;
                        }
                    }
                }
                *((float4*)&sA[r][c16 + 0]) = a0;
                *((float4*)&sA[r][c16 + 4]) = a1;
                *((float4*)&sA[r][c16 + 8]) = a2;
                *((float4*)&sA[r][c16 + 12]) = a3;
                __syncthreads();

                float c[4][4];
#pragma unroll
                for (int i = 0; i < 4; i++)
#pragma unroll
                    for (int j = 0; j < 4; j++) c[i][j] = 0.f;

#pragma unroll 8
                for (int k = 0; k < 64; k++) {
                    float4 b4 = *((const float4*)&sW[k][n0]);
                    float x0 = sA[m0 + 0][k];
                    float x1 = sA[m0 + 1][k];
                    float x2 = sA[m0 + 2][k];
                    float x3 = sA[m0 + 3][k];
                    c[0][0] += x0 * b4.x; c[0][1] += x0 * b4.y; c[0][2] += x0 * b4.z; c[0][3] += x0 * b4.w;
                    c[1][0] += x1 * b4.x; c[1][1] += x1 * b4.y; c[1][2] += x1 * b4.z; c[1][3] += x1 * b4.w;
                    c[2][0] += x2 * b4.x; c[2][1] += x2 * b4.y; c[2][2] += x2 * b4.z; c[2][3] += x2 * b4.w;
                    c[3][0] += x3 * b4.x; c[3][1] += x3 * b4.y; c[3][2] += x3 * b4.z; c[3][3] += x3 * b4.w;
                }

                float* outbuf = dir ? g_bout : g_fout;
#pragma unroll
                for (int i = 0; i < 4; i++) {
                    int mm = tile * 64 + m0 + i;
                    if (mm < cnt) {
                        int slot = start + mm;
                        float dg2 = (float)__ldg(deg + slot);
                        float4 o;
                        o.x = c[i][0] + dg2 * bs.x;
                        o.y = c[i][1] + dg2 * bs.y;
                        o.z = c[i][2] + dg2 * bs.z;
                        o.w = c[i][3] + dg2 * bs.w;
                        *((float4*)(outbuf + (size_t)slot * DD + n0)) = o;
                    }
                }
                __syncthreads();
            }

            // ---- prefetch next phase's indices (prep data; safe pre-barrier) ----
            {
                int ndir = dir, nl = l + 1;
                if (nl == NLVL) { ndir = 1; nl = 1; }
                if (!(dir == 1 && l == NLVL - 1)) {   // no prefetch before pool
                    const int* noff = ndir ? g_boff : g_foff;
                    const int* neptr = ndir ? g_beptr : g_feptr;
                    int nstart = noff[nl];
                    int ncnt = noff[nl + 1] - nstart;
                    int m = (int)blockIdx.x * 64 + r;
                    if (m < ncnt) {
                        int slot = nstart + m;
                        pf_e0 = __ldg(neptr + slot);
                        pf_e1 = __ldg(neptr + slot + 1);
                        int dg = pf_e1 - pf_e0;
                        if (ndir == 0) {
#pragma unroll
                            for (int k = 0; k < PFK; k++)
                                if (k < dg) pf_a[k] = __ldg(g_fsrc + pf_e0 + k);
                        } else {
#pragma unroll
                            for (int k = 0; k < PFK; k++)
                                if (k < dg) {
                                    int2 ee = __ldg(g_bedge + pf_e0 + k);
                                    pf_a[k] = ee.x;
                                    pf_b[k] = ee.y;
                                }
                        }
                    } else { pf_e0 = pf_e1 = 0; }
                }
            }
            grid_bar(base + (++nbar));
        }
    }

    // ---- pool phase ----
    {
        int chunk = (NN + gridDim.x - 1) / gridDim.x;
        int s = blockIdx.x * chunk;
        int e = min(NN, s + chunk);
        if (s < e) {
            int warp = threadIdx.x >> 5;
            int nw = 256 >> 5;
            int len = e - s;
            int wchunk = (len + nw - 1) / nw;
            int ws = s + warp * wchunk;
            int we = min(e, ws + wchunk);
            float2 mx = make_float2(NEGMAX, NEGMAX);
            float2 sm = make_float2(0.f, 0.f);
            int cb = (ws < we) ? batch[ws] : -1;
            for (int n = ws; n < we; n++) {
                int bb = batch[n];
                if (bb != cb) {
                    pool_flush(cb, mx, sm, lane, out);
                    mx = make_float2(NEGMAX, NEGMAX);
                    sm = make_float2(0.f, 0.f);
                    cb = bb;
                }
                if (nt[n] == 1) {
                    const float* basep;
                    if (bl[n] >= 1) {
                        basep = g_bout + (size_t)g_bslot[n] * DD;
                    } else {
                        int fp = g_fslot[n];
                        basep = (fl[n] >= 1)
                            ? g_fout + (size_t)(fp & SLOT_MASK) * DD
                            : g_tab + ((fp >> 20) & 0xF) * DD;
                    }
                    float2 v = *((const float2*)basep + lane);
                    mx.x = fmaxf(mx.x, v.x);
                    mx.y = fmaxf(mx.y, v.y);
                    sm.x += v.x;
                    sm.y += v.y;
                }
            }
            if (cb >= 0) pool_flush(cb, mx, sm, lane, out);
        }
    }
    grid_bar(base + (++nbar));

    // ---- fixup (block 0) ----
    if (blockIdx.x == 0) {
        for (int i = threadIdx.x; i < BBATCH * DD; i += 256) {
            int b = i >> 6, d = i & 63;
            int pos = b * 128 + d;
            unsigned u = __ldcg((const unsigned*)out + pos);
            out[pos] = dec_f(u);
        }
    }
}

// ---------------- PDL launch helper ----------------
template <typename... Args>
static void pdl(void (*kern)(Args...), int grid, int block, Args... args) {
    cudaLaunchConfig_t cfg = {};
    cfg.gridDim = dim3(grid, 1, 1);
    cfg.blockDim = dim3(block, 1, 1);
    cfg.stream = 0;
    cudaLaunchAttribute attr;
    attr.id = cudaLaunchAttributeProgrammaticStreamSerialization;
    attr.val.programmaticStreamSerializationAllowed = 1;
    cfg.attrs = &attr;
    cfg.numAttrs = 1;
    cudaLaunchKernelEx(&cfg, kern, args...);
}

// ---------------- launch ----------------
extern "C" void kernel_launch(void* const* d_in, const int* in_sizes, int n_in,
                              void* d_out, int out_size) {
    const int* nt    = (const int*)d_in[0];
    const int* nip   = (const int*)d_in[1];
    const int* ei    = (const int*)d_in[2];
    const int* fl    = (const int*)d_in[3];
    const int* bl    = (const int*)d_in[4];
    const int* batch = (const int*)d_in[5];
    const float* W_enc = (const float*)d_in[6];
    const float* b_enc = (const float*)d_in[7];
    const float* W_f   = (const float*)d_in[8];
    const float* b_f   = (const float*)d_in[9];
    const float* W_b   = (const float*)d_in[10];
    const float* b_b   = (const float*)d_in[11];
    float* out = (float*)d_out;

    k_zero<<<196, 256>>>(out);
    pdl(k_deg_hist, NB2, 256, ei, fl, bl);
    pdl(k_hscan, 1, 768);
    pdl(k_assign2, NB2, 256, fl, bl, nt, nip);
    pdl(k_scan1, 2 * SCAN_NB, 256);
    pdl(k_scan2p, 1, 256, W_enc, b_enc);
    pdl(k_scan3, 784, 256);
    pdl(k_scatter_e, 1600, 256, ei, fl);
    pdl(k_persist, PGRID, 256, nt, batch, fl, bl, W_f, b_f, W_b, b_b, out);
}

// round 15
// speedup vs baseline: 1.4994x; 1.4994x over previous
#include <cuda_runtime.h>

#define NN 200000
#define EE 400000
#define DD 64
#define BBATCH 16
#define NLVL 12
#define SCAN_NB ((NN + 1023) / 1024)   // 196 (degree scans, 1024/block)
#define NB2 784                        // node-chunk blocks (256 nodes/block)
#define PGRID 296
#define SLOT_MASK 0xFFFFF
#define FOUT_FLAG 0x40000000

// ---------------- device scratch ----------------
__device__ float g_fout[NN * DD];       // slot-indexed forward outputs
__device__ float g_bout[NN * DD];       // slot-indexed backward outputs
__device__ float g_tab[9 * DD];         // 9 distinct f0 rows (nt*3+nip)
__device__ int g_indeg[NN], g_outdeg[NN];
__device__ int g_fslot[NN], g_bslot[NN];     // node -> slot (fslot packs type<<20)
__device__ int g_fdeg[NN], g_bdeg[NN];       // slot-indexed degree
__device__ int g_feptr[NN + 1], g_beptr[NN + 1];
__device__ int g_fcur_e[NN], g_bcur_e[NN];
__device__ int g_fsrc[EE];              // fwd edges by dst-slot: packed fslot[src]
__device__ int2 g_bedge[EE];            // bwd edges by src-slot: (bslot[dst], fidx[dst])
__device__ int g_foff[NLVL + 1], g_boff[NLVL + 1];
__device__ int g_lhist[2 * NLVL * NB2];
__device__ int g_bsum[2][SCAN_NB], g_bsum_s[2][SCAN_NB];
// grid barrier (generation counter survives graph replays)
__device__ unsigned g_cnt = 0;
__device__ volatile unsigned g_gen = 0;

__device__ __forceinline__ unsigned enc_f(float f) {
    unsigned u = __float_as_uint(f);
    return (u & 0x80000000u) ? ~u : (u | 0x80000000u);
}
__device__ __forceinline__ float dec_f(unsigned u) {
    return (u & 0x80000000u) ? __uint_as_float(u & 0x7FFFFFFFu)
                             : __uint_as_float(~u);
}
#define NEGMAX (-3.402823466e38f)

// ---------------- K0: zero degree arrays + init output buffer ----------------
__global__ void k_zero(float* __restrict__ out) {
    int stride = gridDim.x * blockDim.x;
    for (int i = blockIdx.x * blockDim.x + threadIdx.x; i < NN; i += stride) {
        g_indeg[i] = 0;
        g_outdeg[i] = 0;
        if (i < BBATCH * 2 * DD) {
            int col = i & 127;
            ((unsigned*)out)[i] = (col < 64) ? 0x00800000u : 0u;
        }
    }
}

// ---------------- K1: node level hists (pre-sync) + edge degrees (post-sync) ----------------
__global__ void k_deg_hist(const int* __restrict__ ei, const int* __restrict__ fl,
                           const int* __restrict__ bl) {
    __shared__ int sh[2 * NLVL];
    int t = threadIdx.x;
    if (t < 2 * NLVL) sh[t] = 0;
    __syncthreads();
    int idx = blockIdx.x * 256 + t;          // one node per thread
    if (idx < NN) {
        atomicAdd(&sh[fl[idx]], 1);
        atomicAdd(&sh[NLVL + bl[idx]], 1);
    }
    cudaGridDependencySynchronize();         // wait k_zero (g_indeg/outdeg ready)
    int stride = gridDim.x * blockDim.x;
    for (int i = blockIdx.x * blockDim.x + t; i < EE; i += stride) {
        atomicAdd(&g_indeg[ei[EE + i]], 1);
        atomicAdd(&g_outdeg[ei[i]], 1);
    }
    __syncthreads();
    if (t < 2 * NLVL) g_lhist[t * NB2 + blockIdx.x] = sh[t];
}

// ---------------- K2: scan block hists -> per-(blk,lvl) offsets + foff/boff ----------------
__global__ void k_hscan() {
    __shared__ int tot[2 * NLVL];
    __shared__ int off_s[2][NLVL + 1];
    int t = threadIdx.x;
    int wid = t >> 5, lane = t & 31;       // 24 warps
    cudaGridDependencySynchronize();
    int* row = g_lhist + wid * NB2;
    int carry = 0;
#pragma unroll
    for (int r = 0; r < (NB2 + 31) / 32; r++) {
        int idx = r * 32 + lane;
        int v = (idx < NB2) ? row[idx] : 0;
        int incl = v;
#pragma unroll
        for (int o = 1; o < 32; o <<= 1) {
            int n = __shfl_up_sync(0xffffffffu, incl, o);
            if (lane >= o) incl += n;
        }
        if (idx < NB2) row[idx] = incl - v + carry;
        carry += __shfl_sync(0xffffffffu, incl, 31);
    }
    if (lane == 0) tot[wid] = carry;
    __syncthreads();
    if (wid < 2) {
        int hv = (lane < NLVL) ? tot[wid * NLVL + lane] : 0;
        int v = hv;
#pragma unroll
        for (int o = 1; o < 32; o <<= 1) {
            int n = __shfl_up_sync(0xffffffffu, v, o);
            if (lane >= o) v += n;
        }
        int excl = v - hv;
        if (lane <= NLVL) {
            off_s[wid][lane] = excl;
            (wid ? g_boff : g_foff)[lane] = excl;
        }
    }
    __syncthreads();
    int add = off_s[wid / NLVL][wid % NLVL];
#pragma unroll
    for (int r = 0; r < (NB2 + 31) / 32; r++) {
        int idx = r * 32 + lane;
        if (idx < NB2) row[idx] += add;
    }
}

// ---------------- K3: assign slots (pack nt/nip type into fslot) ----------------
__global__ void k_assign2(const int* __restrict__ fl, const int* __restrict__ bl,
                          const int* __restrict__ nt, const int* __restrict__ nip) {
    __shared__ int sc[2 * NLVL];
    int t = threadIdx.x;
    int v = blockIdx.x * 256 + t;            // one node per thread
    int type = 0, flv = 0, blv = 0;
    if (v < NN) {
        type = nt[v] * 3 + nip[v];
        flv = fl[v];
        blv = bl[v];
    }
    cudaGridDependencySynchronize();
    if (t < 2 * NLVL) sc[t] = g_lhist[t * NB2 + blockIdx.x];
    __syncthreads();
    if (v < NN) {
        int s = atomicAdd(&sc[flv], 1);
        g_fslot[v] = s | (type << 20);
        g_fdeg[s] = g_indeg[v];
        int s2 = atomicAdd(&sc[NLVL + blv], 1);
        g_bslot[v] = s2;
        g_bdeg[s2] = g_outdeg[v];
    }
}

// ---------------- K4: block-local exclusive scans of slot degrees ----------------
__global__ void k_scan1() {
    int which = blockIdx.x / SCAN_NB;   // 0 = fdeg, 1 = bdeg
    int blk = blockIdx.x % SCAN_NB;
    const int* deg = which ? g_bdeg : g_fdeg;
    int* ptr = which ? g_beptr : g_feptr;
    __shared__ int sh[256];
    int base = blk * 1024 + threadIdx.x * 4;
    cudaGridDependencySynchronize();
    int v[4];
    int s = 0;
#pragma unroll
    for (int j = 0; j < 4; j++) {
        int idx = base + j;
        v[j] = (idx < NN) ? deg[idx] : 0;
        s += v[j];
    }
    sh[threadIdx.x] = s;
    __syncthreads();
    for (int off = 1; off < 256; off <<= 1) {
        int t = 0;
        if (threadIdx.x >= off) t = sh[threadIdx.x - off];
        __syncthreads();
        sh[threadIdx.x] += t;
        __syncthreads();
    }
    int run = sh[threadIdx.x] - s;
#pragma unroll
    for (int j = 0; j < 4; j++) {
        int idx = base + j;
        if (idx < NN) ptr[idx] = run;
        run += v[j];
    }
    if (threadIdx.x == 255) g_bsum[which][blk] = sh[255];
}

// ---------------- K5: build f0 table (pre-sync) + scan of block sums ----------------
__global__ void k_scan2p(const float* __restrict__ Wenc, const float* __restrict__ benc) {
    __shared__ int sh[256];
    int t = threadIdx.x;
    for (int i = t; i < 9 * DD; i += 256) {
        int ty = i >> 6, d = i & 63;
        g_tab[i] = (float)(ty / 3) * Wenc[d] + (float)(ty % 3) * Wenc[64 + d] + benc[d];
    }
    cudaGridDependencySynchronize();
#pragma unroll
    for (int w = 0; w < 2; w++) {
        int v = (t < SCAN_NB) ? g_bsum[w][t] : 0;
        sh[t] = v;
        __syncthreads();
        for (int off = 1; off < 256; off <<= 1) {
            int x = 0;
            if (t >= off) x = sh[t - off];
            __syncthreads();
            sh[t] += x;
            __syncthreads();
        }
        if (t < SCAN_NB) g_bsum_s[w][t] = sh[t] - v;
        __syncthreads();
    }
    if (t == 0) { g_feptr[NN] = EE; g_beptr[NN] = EE; }
}

// ---------------- K6: add block offsets, init edge-scatter cursors ----------------
__global__ void k_scan3() {
    int stride = gridDim.x * blockDim.x;
    cudaGridDependencySynchronize();
    for (int i = blockIdx.x * blockDim.x + threadIdx.x; i < 2 * NN; i += stride) {
        if (i < NN) {
            int v = g_feptr[i] + g_bsum_s[0][i >> 10];
            g_feptr[i] = v;
            g_fcur_e[i] = v;
        } else {
            int j = i - NN;
            int v = g_beptr[j] + g_bsum_s[1][j >> 10];
            g_beptr[j] = v;
            g_bcur_e[j] = v;
        }
    }
}

// ---------------- K7: scatter edges into slot-ordered lists ----------------
__global__ void k_scatter_e(const int* __restrict__ ei, const int* __restrict__ fl) {
    int stride = gridDim.x * blockDim.x;
    cudaGridDependencySynchronize();
    for (int i = blockIdx.x * blockDim.x + threadIdx.x; i < EE; i += stride) {
        int src = ei[i], dst = ei[EE + i];
        int fp_src = g_fslot[src];             // packed slot | type<<20
        int fp_dst = g_fslot[dst];
        int p = atomicAdd(&g_fcur_e[fp_dst & SLOT_MASK], 1);
        g_fsrc[p] = fp_src;
        int bs_src = g_bslot[src];
        int bs_dst = g_bslot[dst];
        int q = atomicAdd(&g_bcur_e[bs_src], 1);
        int fidx = fp_dst | ((fl[dst] >= 1) ? FOUT_FLAG : 0);
        g_bedge[q] = make_int2(bs_dst, fidx);
    }
}

// ---------------- grid-wide software barrier (volatile + nanosleep, proven) ----------------
__device__ __forceinline__ void grid_bar(unsigned target) {
    __threadfence();
    __syncthreads();
    if (threadIdx.x == 0) {
        unsigned t = atomicAdd(&g_cnt, 1u);
        if (t == (unsigned)gridDim.x - 1u) {
            g_cnt = 0u;
            __threadfence();
            g_gen = target;
        } else {
            while (g_gen != target) __nanosleep(64);
        }
        __threadfence();
    }
    __syncthreads();
}

__device__ __forceinline__ void pool_flush(int cb, float2 mx, float2 sm, int lane,
                                           float* out) {
    int d = 2 * lane;
    unsigned* uo = (unsigned*)out;
    atomicMax(&uo[cb * 128 + d], enc_f(mx.x));
    atomicMax(&uo[cb * 128 + d + 1], enc_f(mx.y));
    atomicAdd(&out[cb * 128 + 64 + d], sm.x);
    atomicAdd(&out[cb * 128 + 64 + d + 1], sm.y);
}

// packed fp32x2 FMA: d += a * b per 32-bit lane (Blackwell FFMA2)
__device__ __forceinline__ void fma2(unsigned long long& d, unsigned long long a,
                                     unsigned long long b) {
    asm("fma.rn.f32x2 %0, %1, %2, %0;" : "+l"(d) : "l"(a), "l"(b));
}
__device__ __forceinline__ unsigned long long bcast2(float a) {
    unsigned long long r;
    asm("mov.b64 %0, {%1, %1};" : "=l"(r) : "r"(__float_as_uint(a)));
    return r;
}

// ---------------- persistent: 22 fused levels + pool + fixup ----------------
__global__ void __launch_bounds__(256, 2) k_persist(
    const int* __restrict__ nt, const int* __restrict__ batch,
    const int* __restrict__ fl, const int* __restrict__ bl,
    const float* __restrict__ W_f, const float* __restrict__ b_f,
    const float* __restrict__ W_b, const float* __restrict__ b_b,
    float* __restrict__ out) {

    __shared__ float sW[64][64];
    __shared__ float sA[64][68];

    const int lane = threadIdx.x & 31;
    const int tx = threadIdx.x & 15, ty = threadIdx.x >> 4;
    const int n0 = tx << 2, m0 = ty << 2;
    const int r = threadIdx.x >> 2;
    const int c16 = (threadIdx.x & 3) << 4;

    // pre-sync prologue: dir-0 weights are graph-constant inputs
    for (int i = threadIdx.x; i < 4096; i += 256) sW[i >> 6][i & 63] = W_f[i];

    cudaGridDependencySynchronize();

    unsigned base = 0, nbar = 0;
    if (threadIdx.x == 0) base = g_gen;

    for (int dir = 0; dir < 2; dir++) {
        const float* bias = dir ? b_b : b_f;
        const int* off = dir ? g_boff : g_foff;
        const int* eptr = dir ? g_beptr : g_feptr;
        const int* deg = dir ? g_bdeg : g_fdeg;

        if (dir == 1) {
            // sW free to overwrite: last read preceded the prior grid_bar's syncthreads
            for (int i = threadIdx.x; i < 4096; i += 256) sW[i >> 6][i & 63] = W_b[i];
        }
        float4 bs = *(const float4*)(bias + n0);
        int off1 = off[1];

        for (int l = 1; l < NLVL; l++) {
            int start = off[l];
            int cnt = off[l + 1] - start;
            int ntiles = (cnt + 63) >> 6;

            for (int tile = blockIdx.x; tile < ntiles; tile += gridDim.x) {
                int m = tile * 64 + r;
                float4 a0 = {0,0,0,0}, a1 = {0,0,0,0}, a2 = {0,0,0,0}, a3 = {0,0,0,0};
                if (m < cnt) {
                    int slot = start + m;
                    int e0 = __ldg(eptr + slot), e1 = __ldg(eptr + slot + 1);
                    if (dir == 0) {
                        for (int e = e0; e < e1; e++) {
                            int v = __ldg(g_fsrc + e);
                            int s = v & SLOT_MASK;
                            const float* hb = (s >= off1 && s < start)
                                ? g_fout + (size_t)s * DD
                                : g_tab + ((v >> 20) & 0xF) * DD;
                            const float4* b = (const float4*)(hb + c16);
                            float4 v0 = b[0], v1 = b[1], v2 = b[2], v3 = b[3];
                            a0.x += v0.x; a0.y += v0.y; a0.z += v0.z; a0.w += v0.w;
                            a1.x += v1.x; a1.y += v1.y; a1.z += v1.z; a1.w += v1.w;
                            a2.x += v2.x; a2.y += v2.y; a2.z += v2.z; a2.w += v2.w;
                            a3.x += v3.x; a3.y += v3.y; a3.z += v3.z; a3.w += v3.w;
                        }
                    } else {
                        for (int e = e0; e < e1; e++) {
                            int2 ee = __ldg(g_bedge + e);
                            int s = ee.x;
                            const float* hb;
                            if (s >= off1 && s < start) {
                                hb = g_bout + (size_t)s * DD;
                            } else {
                                int f = ee.y;
                                hb = (f & FOUT_FLAG)
                                    ? g_fout + (size_t)(f & SLOT_MASK) * DD
                                    : g_tab + ((f >> 20) & 0xF) * DD;
                            }
                            const float4* b = (const float4*)(hb + c16);
                            float4 v0 = b[0], v1 = b[1], v2 = b[2], v3 = b[3];
                            a0.x += v0.x; a0.y += v0.y; a0.z += v0.z; a0.w += v0.w;
                            a1.x += v1.x; a1.y += v1.y; a1.z += v1.z; a1.w += v1.w;
                            a2.x += v2.x; a2.y += v2.y; a2.z += v2.z; a2.w += v2.w;
                            a3.x += v3.x; a3.y += v3.y; a3.z += v3.z; a3.w += v3.w;
                        }
                    }
                }
                *((float4*)&sA[r][c16 + 0]) = a0;
                *((float4*)&sA[r][c16 + 4]) = a1;
                *((float4*)&sA[r][c16 + 8]) = a2;
                *((float4*)&sA[r][c16 + 12]) = a3;
                __syncthreads();

                // packed f32x2 GEMM: c[i][pair] accumulators, k vectorized by 4
                unsigned long long cc[4][2] = {};
#pragma unroll 4
                for (int k4 = 0; k4 < 64; k4 += 4) {
                    ulonglong2 bb0 = *(const ulonglong2*)&sW[k4 + 0][n0];
                    ulonglong2 bb1 = *(const ulonglong2*)&sW[k4 + 1][n0];
                    ulonglong2 bb2 = *(const ulonglong2*)&sW[k4 + 2][n0];
                    ulonglong2 bb3 = *(const ulonglong2*)&sW[k4 + 3][n0];
                    float4 av[4];
#pragma unroll
                    for (int i = 0; i < 4; i++)
                        av[i] = *(const float4*)&sA[m0 + i][k4];
#pragma unroll
                    for (int i = 0; i < 4; i++) {
                        unsigned long long ap;
                        ap = bcast2(av[i].x);
                        fma2(cc[i][0], ap, bb0.x); fma2(cc[i][1], ap, bb0.y);
                        ap = bcast2(av[i].y);
                        fma2(cc[i][0], ap, bb1.x); fma2(cc[i][1], ap, bb1.y);
                        ap = bcast2(av[i].z);
                        fma2(cc[i][0], ap, bb2.x); fma2(cc[i][1], ap, bb2.y);
                        ap = bcast2(av[i].w);
                        fma2(cc[i][0], ap, bb3.x); fma2(cc[i][1], ap, bb3.y);
                    }
                }

                float* outbuf = dir ? g_bout : g_fout;
#pragma unroll
                for (int i = 0; i < 4; i++) {
                    int mm = tile * 64 + m0 + i;
                    if (mm < cnt) {
                        int slot = start + mm;
                        float dg = (float)__ldg(deg + slot);
                        float4 o;
                        o.x = __uint_as_float((unsigned)(cc[i][0] & 0xFFFFFFFFull)) + dg * bs.x;
                        o.y = __uint_as_float((unsigned)(cc[i][0] >> 32)) + dg * bs.y;
                        o.z = __uint_as_float((unsigned)(cc[i][1] & 0xFFFFFFFFull)) + dg * bs.z;
                        o.w = __uint_as_float((unsigned)(cc[i][1] >> 32)) + dg * bs.w;
                        *((float4*)(outbuf + (size_t)slot * DD + n0)) = o;
                    }
                }
                __syncthreads();
            }
            grid_bar(base + (++nbar));
        }
    }

    // ---- pool phase ----
    {
        int chunk = (NN + gridDim.x - 1) / gridDim.x;
        int s = blockIdx.x * chunk;
        int e = min(NN, s + chunk);
        if (s < e) {
            int warp = threadIdx.x >> 5;
            int nw = 256 >> 5;
            int len = e - s;
            int wchunk = (len + nw - 1) / nw;
            int ws = s + warp * wchunk;
            int we = min(e, ws + wchunk);
            float2 mx = make_float2(NEGMAX, NEGMAX);
            float2 sm = make_float2(0.f, 0.f);
            int cb = (ws < we) ? batch[ws] : -1;
            for (int n = ws; n < we; n++) {
                int bb = batch[n];
                if (bb != cb) {
                    pool_flush(cb, mx, sm, lane, out);
                    mx = make_float2(NEGMAX, NEGMAX);
                    sm = make_float2(0.f, 0.f);
                    cb = bb;
                }
                if (nt[n] == 1) {
                    const float* basep;
                    if (bl[n] >= 1) {
                        basep = g_bout + (size_t)g_bslot[n] * DD;
                    } else {
                        int fp = g_fslot[n];
                        basep = (fl[n] >= 1)
                            ? g_fout + (size_t)(fp & SLOT_MASK) * DD
                            : g_tab + ((fp >> 20) & 0xF) * DD;
                    }
                    float2 v = *((const float2*)basep + lane);
                    mx.x = fmaxf(mx.x, v.x);
                    mx.y = fmaxf(mx.y, v.y);
                    sm.x += v.x;
                    sm.y += v.y;
                }
            }
            if (cb >= 0) pool_flush(cb, mx, sm, lane, out);
        }
    }
    grid_bar(base + (++nbar));

    // ---- fixup (block 0) ----
    if (blockIdx.x == 0) {
        for (int i = threadIdx.x; i < BBATCH * DD; i += 256) {
            int b = i >> 6, d = i & 63;
            int pos = b * 128 + d;
            unsigned u = __ldcg((const unsigned*)out + pos);
            out[pos] = dec_f(u);
        }
    }
}

// ---------------- PDL launch helper ----------------
template <typename... Args>
static void pdl(void (*kern)(Args...), int grid, int block, Args... args) {
    cudaLaunchConfig_t cfg = {};
    cfg.gridDim = dim3(grid, 1, 1);
    cfg.blockDim = dim3(block, 1, 1);
    cfg.stream = 0;
    cudaLaunchAttribute attr;
    attr.id = cudaLaunchAttributeProgrammaticStreamSerialization;
    attr.val.programmaticStreamSerializationAllowed = 1;
    cfg.attrs = &attr;
    cfg.numAttrs = 1;
    cudaLaunchKernelEx(&cfg, kern, args...);
}

// ---------------- launch ----------------
extern "C" void kernel_launch(void* const* d_in, const int* in_sizes, int n_in,
                              void* d_out, int out_size) {
    const int* nt    = (const int*)d_in[0];
    const int* nip   = (const int*)d_in[1];
    const int* ei    = (const int*)d_in[2];
    const int* fl    = (const int*)d_in[3];
    const int* bl    = (const int*)d_in[4];
    const int* batch = (const int*)d_in[5];
    const float* W_enc = (const float*)d_in[6];
    const float* b_enc = (const float*)d_in[7];
    const float* W_f   = (const float*)d_in[8];
    const float* b_f   = (const float*)d_in[9];
    const float* W_b   = (const float*)d_in[10];
    const float* b_b   = (const float*)d_in[11];
    float* out = (float*)d_out;

    k_zero<<<196, 256>>>(out);
    pdl(k_deg_hist, NB2, 256, ei, fl, bl);
    pdl(k_hscan, 1, 768);
    pdl(k_assign2, NB2, 256, fl, bl, nt, nip);
    pdl(k_scan1, 2 * SCAN_NB, 256);
    pdl(k_scan2p, 1, 256, W_enc, b_enc);
    pdl(k_scan3, 784, 256);
    pdl(k_scatter_e, 1600, 256, ei, fl);
    pdl(k_persist, PGRID, 256, nt, batch, fl, bl, W_f, b_f, W_b, b_b, out);
}

// round 16
// speedup vs baseline: 1.5343x; 1.0232x over previous
#include <cuda_runtime.h>

#define NN 200000
#define EE 400000
#define DD 64
#define BBATCH 16
#define NLVL 12
#define SCAN_NB ((NN + 1023) / 1024)   // 196 (degree scans, 1024/block)
#define NB2 784                        // node-chunk blocks (256 nodes/block)
#define PGRID 592                      // 148 SMs x 4 CTAs (128 thr each)
#define TROWS 32                       // tile rows
#define SLOT_MASK 0xFFFFF
#define FOUT_FLAG 0x40000000

// ---------------- device scratch ----------------
__device__ float g_fout[NN * DD];       // slot-indexed forward outputs
__device__ float g_bout[NN * DD];       // slot-indexed backward outputs
__device__ float g_tab[9 * DD];         // 9 distinct f0 rows (nt*3+nip)
__device__ int g_indeg[NN], g_outdeg[NN];
__device__ int g_fslot[NN], g_bslot[NN];     // node -> slot (fslot packs type<<20)
__device__ int g_fdeg[NN], g_bdeg[NN];       // slot-indexed degree
__device__ int g_feptr[NN + 1], g_beptr[NN + 1];
__device__ int g_fcur_e[NN], g_bcur_e[NN];
__device__ int g_fsrc[EE];              // fwd edges by dst-slot: packed fslot[src]
__device__ int2 g_bedge[EE];            // bwd edges by src-slot: (bslot[dst], fidx[dst])
__device__ int g_foff[NLVL + 1], g_boff[NLVL + 1];
__device__ int g_lhist[2 * NLVL * NB2];
__device__ int g_bsum[2][SCAN_NB], g_bsum_s[2][SCAN_NB];
// grid barrier (generation counter survives graph replays)
__device__ unsigned g_cnt = 0;
__device__ volatile unsigned g_gen = 0;

__device__ __forceinline__ unsigned enc_f(float f) {
    unsigned u = __float_as_uint(f);
    return (u & 0x80000000u) ? ~u : (u | 0x80000000u);
}
__device__ __forceinline__ float dec_f(unsigned u) {
    return (u & 0x80000000u) ? __uint_as_float(u & 0x7FFFFFFFu)
                             : __uint_as_float(~u);
}
#define NEGMAX (-3.402823466e38f)

// ---------------- K0: zero degree arrays + init output buffer ----------------
__global__ void k_zero(float* __restrict__ out) {
    int stride = gridDim.x * blockDim.x;
    for (int i = blockIdx.x * blockDim.x + threadIdx.x; i < NN; i += stride) {
        g_indeg[i] = 0;
        g_outdeg[i] = 0;
        if (i < BBATCH * 2 * DD) {
            int col = i & 127;
            ((unsigned*)out)[i] = (col < 64) ? 0x00800000u : 0u;
        }
    }
}

// ---------------- K1: node level hists (pre-sync) + edge degrees (post-sync) ----------------
__global__ void k_deg_hist(const int* __restrict__ ei, const int* __restrict__ fl,
                           const int* __restrict__ bl) {
    __shared__ int sh[2 * NLVL];
    int t = threadIdx.x;
    if (t < 2 * NLVL) sh[t] = 0;
    __syncthreads();
    int idx = blockIdx.x * 256 + t;          // one node per thread
    if (idx < NN) {
        atomicAdd(&sh[fl[idx]], 1);
        atomicAdd(&sh[NLVL + bl[idx]], 1);
    }
    cudaGridDependencySynchronize();         // wait k_zero (g_indeg/outdeg ready)
    int stride = gridDim.x * blockDim.x;
    for (int i = blockIdx.x * blockDim.x + t; i < EE; i += stride) {
        atomicAdd(&g_indeg[ei[EE + i]], 1);
        atomicAdd(&g_outdeg[ei[i]], 1);
    }
    __syncthreads();
    if (t < 2 * NLVL) g_lhist[t * NB2 + blockIdx.x] = sh[t];
}

// ---------------- K2: scan block hists -> per-(blk,lvl) offsets + foff/boff ----------------
__global__ void k_hscan() {
    __shared__ int tot[2 * NLVL];
    __shared__ int off_s[2][NLVL + 1];
    int t = threadIdx.x;
    int wid = t >> 5, lane = t & 31;       // 24 warps
    cudaGridDependencySynchronize();
    int* row = g_lhist + wid * NB2;
    int carry = 0;
#pragma unroll
    for (int r = 0; r < (NB2 + 31) / 32; r++) {
        int idx = r * 32 + lane;
        int v = (idx < NB2) ? row[idx] : 0;
        int incl = v;
#pragma unroll
        for (int o = 1; o < 32; o <<= 1) {
            int n = __shfl_up_sync(0xffffffffu, incl, o);
            if (lane >= o) incl += n;
        }
        if (idx < NB2) row[idx] = incl - v + carry;
        carry += __shfl_sync(0xffffffffu, incl, 31);
    }
    if (lane == 0) tot[wid] = carry;
    __syncthreads();
    if (wid < 2) {
        int hv = (lane < NLVL) ? tot[wid * NLVL + lane] : 0;
        int v = hv;
#pragma unroll
        for (int o = 1; o < 32; o <<= 1) {
            int n = __shfl_up_sync(0xffffffffu, v, o);
            if (lane >= o) v += n;
        }
        int excl = v - hv;
        if (lane <= NLVL) {
            off_s[wid][lane] = excl;
            (wid ? g_boff : g_foff)[lane] = excl;
        }
    }
    __syncthreads();
    int add = off_s[wid / NLVL][wid % NLVL];
#pragma unroll
    for (int r = 0; r < (NB2 + 31) / 32; r++) {
        int idx = r * 32 + lane;
        if (idx < NB2) row[idx] += add;
    }
}

// ---------------- K3: assign slots (pack nt/nip type into fslot) ----------------
__global__ void k_assign2(const int* __restrict__ fl, const int* __restrict__ bl,
                          const int* __restrict__ nt, const int* __restrict__ nip) {
    __shared__ int sc[2 * NLVL];
    int t = threadIdx.x;
    int v = blockIdx.x * 256 + t;            // one node per thread
    int type = 0, flv = 0, blv = 0;
    if (v < NN) {
        type = nt[v] * 3 + nip[v];
        flv = fl[v];
        blv = bl[v];
    }
    cudaGridDependencySynchronize();
    if (t < 2 * NLVL) sc[t] = g_lhist[t * NB2 + blockIdx.x];
    __syncthreads();
    if (v < NN) {
        int s = atomicAdd(&sc[flv], 1);
        g_fslot[v] = s | (type << 20);
        g_fdeg[s] = g_indeg[v];
        int s2 = atomicAdd(&sc[NLVL + blv], 1);
        g_bslot[v] = s2;
        g_bdeg[s2] = g_outdeg[v];
    }
}

// ---------------- K4: block-local exclusive scans of slot degrees ----------------
__global__ void k_scan1() {
    int which = blockIdx.x / SCAN_NB;   // 0 = fdeg, 1 = bdeg
    int blk = blockIdx.x % SCAN_NB;
    const int* deg = which ? g_bdeg : g_fdeg;
    int* ptr = which ? g_beptr : g_feptr;
    __shared__ int sh[256];
    int base = blk * 1024 + threadIdx.x * 4;
    cudaGridDependencySynchronize();
    int v[4];
    int s = 0;
#pragma unroll
    for (int j = 0; j < 4; j++) {
        int idx = base + j;
        v[j] = (idx < NN) ? deg[idx] : 0;
        s += v[j];
    }
    sh[threadIdx.x] = s;
    __syncthreads();
    for (int off = 1; off < 256; off <<= 1) {
        int t = 0;
        if (threadIdx.x >= off) t = sh[threadIdx.x - off];
        __syncthreads();
        sh[threadIdx.x] += t;
        __syncthreads();
    }
    int run = sh[threadIdx.x] - s;
#pragma unroll
    for (int j = 0; j < 4; j++) {
        int idx = base + j;
        if (idx < NN) ptr[idx] = run;
        run += v[j];
    }
    if (threadIdx.x == 255) g_bsum[which][blk] = sh[255];
}

// ---------------- K5: build f0 table (pre-sync) + scan of block sums ----------------
__global__ void k_scan2p(const float* __restrict__ Wenc, const float* __restrict__ benc) {
    __shared__ int sh[256];
    int t = threadIdx.x;
    for (int i = t; i < 9 * DD; i += 256) {
        int ty = i >> 6, d = i & 63;
        g_tab[i] = (float)(ty / 3) * Wenc[d] + (float)(ty % 3) * Wenc[64 + d] + benc[d];
    }
    cudaGridDependencySynchronize();
#pragma unroll
    for (int w = 0; w < 2; w++) {
        int v = (t < SCAN_NB) ? g_bsum[w][t] : 0;
        sh[t] = v;
        __syncthreads();
        for (int off = 1; off < 256; off <<= 1) {
            int x = 0;
            if (t >= off) x = sh[t - off];
            __syncthreads();
            sh[t] += x;
            __syncthreads();
        }
        if (t < SCAN_NB) g_bsum_s[w][t] = sh[t] - v;
        __syncthreads();
    }
    if (t == 0) { g_feptr[NN] = EE; g_beptr[NN] = EE; }
}

// ---------------- K6: add block offsets, init edge-scatter cursors ----------------
__global__ void k_scan3() {
    int stride = gridDim.x * blockDim.x;
    cudaGridDependencySynchronize();
    for (int i = blockIdx.x * blockDim.x + threadIdx.x; i < 2 * NN; i += stride) {
        if (i < NN) {
            int v = g_feptr[i] + g_bsum_s[0][i >> 10];
            g_feptr[i] = v;
            g_fcur_e[i] = v;
        } else {
            int j = i - NN;
            int v = g_beptr[j] + g_bsum_s[1][j >> 10];
            g_beptr[j] = v;
            g_bcur_e[j] = v;
        }
    }
}

// ---------------- K7: scatter edges into slot-ordered lists ----------------
__global__ void k_scatter_e(const int* __restrict__ ei, const int* __restrict__ fl) {
    int stride = gridDim.x * blockDim.x;
    cudaGridDependencySynchronize();
    for (int i = blockIdx.x * blockDim.x + threadIdx.x; i < EE; i += stride) {
        int src = ei[i], dst = ei[EE + i];
        int fp_src = g_fslot[src];             // packed slot | type<<20
        int fp_dst = g_fslot[dst];
        int p = atomicAdd(&g_fcur_e[fp_dst & SLOT_MASK], 1);
        g_fsrc[p] = fp_src;
        int bs_src = g_bslot[src];
        int bs_dst = g_bslot[dst];
        int q = atomicAdd(&g_bcur_e[bs_src], 1);
        int fidx = fp_dst | ((fl[dst] >= 1) ? FOUT_FLAG : 0);
        g_bedge[q] = make_int2(bs_dst, fidx);
    }
}

// ---------------- grid-wide software barrier (volatile + nanosleep, proven) ----------------
__device__ __forceinline__ void grid_bar(unsigned target) {
    __threadfence();
    __syncthreads();
    if (threadIdx.x == 0) {
        unsigned t = atomicAdd(&g_cnt, 1u);
        if (t == (unsigned)gridDim.x - 1u) {
            g_cnt = 0u;
            __threadfence();
            g_gen = target;
        } else {
            while (g_gen != target) __nanosleep(64);
        }
        __threadfence();
    }
    __syncthreads();
}

__device__ __forceinline__ void pool_flush(int cb, float2 mx, float2 sm, int lane,
                                           float* out) {
    int d = 2 * lane;
    unsigned* uo = (unsigned*)out;
    atomicMax(&uo[cb * 128 + d], enc_f(mx.x));
    atomicMax(&uo[cb * 128 + d + 1], enc_f(mx.y));
    atomicAdd(&out[cb * 128 + 64 + d], sm.x);
    atomicAdd(&out[cb * 128 + 64 + d + 1], sm.y);
}

// packed fp32x2 FMA: d += a * b per 32-bit lane (Blackwell FFMA2)
__device__ __forceinline__ void fma2(unsigned long long& d, unsigned long long a,
                                     unsigned long long b) {
    asm("fma.rn.f32x2 %0, %1, %2, %0;" : "+l"(d) : "l"(a), "l"(b));
}
__device__ __forceinline__ unsigned long long bcast2(float a) {
    unsigned long long r;
    asm("mov.b64 %0, {%1, %1};" : "=l"(r) : "r"(__float_as_uint(a)));
    return r;
}

// ---------------- persistent: 22 fused levels + pool + fixup ----------------
__global__ void __launch_bounds__(128, 4) k_persist(
    const int* __restrict__ nt, const int* __restrict__ batch,
    const int* __restrict__ fl, const int* __restrict__ bl,
    const float* __restrict__ W_f, const float* __restrict__ b_f,
    const float* __restrict__ W_b, const float* __restrict__ b_b,
    float* __restrict__ out) {

    __shared__ float sW[64][64];
    __shared__ float sA[TROWS][68];

    const int lane = threadIdx.x & 31;
    const int tx = threadIdx.x & 15, ty = threadIdx.x >> 4;   // ty 0..7
    const int n0 = tx << 2, m0 = ty << 2;                     // m0 0..28
    const int r = threadIdx.x >> 2;                           // 0..31
    const int c16 = (threadIdx.x & 3) << 4;

    // pre-sync prologue: dir-0 weights are graph-constant inputs
    for (int i = threadIdx.x; i < 4096; i += 128) sW[i >> 6][i & 63] = W_f[i];

    cudaGridDependencySynchronize();

    unsigned base = 0, nbar = 0;
    if (threadIdx.x == 0) base = g_gen;

    // eptr prefetch for first phase (dir 0, level 1); index arrays immutable here
    int pf_e0 = 0, pf_e1 = 0;
    {
        int start = g_foff[1];
        int cnt = g_foff[2] - start;
        int m = (int)blockIdx.x * TROWS + r;
        if (m < cnt) {
            pf_e0 = __ldg(g_feptr + start + m);
            pf_e1 = __ldg(g_feptr + start + m + 1);
        }
    }

    for (int dir = 0; dir < 2; dir++) {
        const float* bias = dir ? b_b : b_f;
        const int* off = dir ? g_boff : g_foff;
        const int* eptr = dir ? g_beptr : g_feptr;
        const int* deg = dir ? g_bdeg : g_fdeg;

        if (dir == 1) {
            // sW free to overwrite: last read preceded the prior grid_bar's syncthreads
            for (int i = threadIdx.x; i < 4096; i += 128) sW[i >> 6][i & 63] = W_b[i];
        }
        float4 bs = *(const float4*)(bias + n0);
        int off1 = off[1];

        for (int l = 1; l < NLVL; l++) {
            int start = off[l];
            int cnt = off[l + 1] - start;
            int ntiles = (cnt + TROWS - 1) / TROWS;

            for (int tile = blockIdx.x; tile < ntiles; tile += gridDim.x) {
                int m = tile * TROWS + r;
                float4 a0 = {0,0,0,0}, a1 = {0,0,0,0}, a2 = {0,0,0,0}, a3 = {0,0,0,0};
                if (m < cnt) {
                    int slot = start + m;
                    int e0, e1;
                    if (tile == (int)blockIdx.x) { e0 = pf_e0; e1 = pf_e1; }
                    else { e0 = __ldg(eptr + slot); e1 = __ldg(eptr + slot + 1); }
                    if (dir == 0) {
                        for (int e = e0; e < e1; e++) {
                            int v = __ldg(g_fsrc + e);
                            int s = v & SLOT_MASK;
                            const float* hb = (s >= off1 && s < start)
                                ? g_fout + (size_t)s * DD
                                : g_tab + ((v >> 20) & 0xF) * DD;
                            const float4* b = (const float4*)(hb + c16);
                            float4 v0 = b[0], v1 = b[1], v2 = b[2], v3 = b[3];
                            a0.x += v0.x; a0.y += v0.y; a0.z += v0.z; a0.w += v0.w;
                            a1.x += v1.x; a1.y += v1.y; a1.z += v1.z; a1.w += v1.w;
                            a2.x += v2.x; a2.y += v2.y; a2.z += v2.z; a2.w += v2.w;
                            a3.x += v3.x; a3.y += v3.y; a3.z += v3.z; a3.w += v3.w;
                        }
                    } else {
                        for (int e = e0; e < e1; e++) {
                            int2 ee = __ldg(g_bedge + e);
                            int s = ee.x;
                            const float* hb;
                            if (s >= off1 && s < start) {
                                hb = g_bout + (size_t)s * DD;
                            } else {
                                int f = ee.y;
                                hb = (f & FOUT_FLAG)
                                    ? g_fout + (size_t)(f & SLOT_MASK) * DD
                                    : g_tab + ((f >> 20) & 0xF) * DD;
                            }
                            const float4* b = (const float4*)(hb + c16);
                            float4 v0 = b[0], v1 = b[1], v2 = b[2], v3 = b[3];
                            a0.x += v0.x; a0.y += v0.y; a0.z += v0.z; a0.w += v0.w;
                            a1.x += v1.x; a1.y += v1.y; a1.z += v1.z; a1.w += v1.w;
                            a2.x += v2.x; a2.y += v2.y; a2.z += v2.z; a2.w += v2.w;
                            a3.x += v3.x; a3.y += v3.y; a3.z += v3.z; a3.w += v3.w;
                        }
                    }
                }
                *((float4*)&sA[r][c16 + 0]) = a0;
                *((float4*)&sA[r][c16 + 4]) = a1;
                *((float4*)&sA[r][c16 + 8]) = a2;
                *((float4*)&sA[r][c16 + 12]) = a3;
                __syncthreads();

                // packed f32x2 GEMM: c[i][pair] accumulators, k vectorized by 4
                unsigned long long cc[4][2] = {};
#pragma unroll 4
                for (int k4 = 0; k4 < 64; k4 += 4) {
                    ulonglong2 bb0 = *(const ulonglong2*)&sW[k4 + 0][n0];
                    ulonglong2 bb1 = *(const ulonglong2*)&sW[k4 + 1][n0];
                    ulonglong2 bb2 = *(const ulonglong2*)&sW[k4 + 2][n0];
                    ulonglong2 bb3 = *(const ulonglong2*)&sW[k4 + 3][n0];
                    float4 av[4];
#pragma unroll
                    for (int i = 0; i < 4; i++)
                        av[i] = *(const float4*)&sA[m0 + i][k4];
#pragma unroll
                    for (int i = 0; i < 4; i++) {
                        unsigned long long ap;
                        ap = bcast2(av[i].x);
                        fma2(cc[i][0], ap, bb0.x); fma2(cc[i][1], ap, bb0.y);
                        ap = bcast2(av[i].y);
                        fma2(cc[i][0], ap, bb1.x); fma2(cc[i][1], ap, bb1.y);
                        ap = bcast2(av[i].z);
                        fma2(cc[i][0], ap, bb2.x); fma2(cc[i][1], ap, bb2.y);
                        ap = bcast2(av[i].w);
                        fma2(cc[i][0], ap, bb3.x); fma2(cc[i][1], ap, bb3.y);
                    }
                }

                float* outbuf = dir ? g_bout : g_fout;
#pragma unroll
                for (int i = 0; i < 4; i++) {
                    int mm = tile * TROWS + m0 + i;
                    if (mm < cnt) {
                        int slot = start + mm;
                        float dg = (float)__ldg(deg + slot);
                        float4 o;
                        o.x = __uint_as_float((unsigned)(cc[i][0] & 0xFFFFFFFFull)) + dg * bs.x;
                        o.y = __uint_as_float((unsigned)(cc[i][0] >> 32)) + dg * bs.y;
                        o.z = __uint_as_float((unsigned)(cc[i][1] & 0xFFFFFFFFull)) + dg * bs.z;
                        o.w = __uint_as_float((unsigned)(cc[i][1] >> 32)) + dg * bs.w;
                        *((float4*)(outbuf + (size_t)slot * DD + n0)) = o;
                    }
                }
                __syncthreads();
            }

            // ---- eptr prefetch for next phase (index arrays immutable) ----
            {
                int ndir = dir, nl = l + 1;
                if (nl == NLVL) { ndir = 1; nl = 1; }
                pf_e0 = 0; pf_e1 = 0;
                if (!(dir == 1 && l == NLVL - 1)) {
                    const int* noff = ndir ? g_boff : g_foff;
                    const int* neptr = ndir ? g_beptr : g_feptr;
                    int nstart = noff[nl];
                    int ncnt = noff[nl + 1] - nstart;
                    int m = (int)blockIdx.x * TROWS + r;
                    if (m < ncnt) {
                        pf_e0 = __ldg(neptr + nstart + m);
                        pf_e1 = __ldg(neptr + nstart + m + 1);
                    }
                }
            }
            grid_bar(base + (++nbar));
        }
    }

    // ---- pool phase ----
    {
        int chunk = (NN + gridDim.x - 1) / gridDim.x;
        int s = blockIdx.x * chunk;
        int e = min(NN, s + chunk);
        if (s < e) {
            int warp = threadIdx.x >> 5;
            int nw = 128 >> 5;
            int len = e - s;
            int wchunk = (len + nw - 1) / nw;
            int ws = s + warp * wchunk;
            int we = min(e, ws + wchunk);
            float2 mx = make_float2(NEGMAX, NEGMAX);
            float2 sm = make_float2(0.f, 0.f);
            int cb = (ws < we) ? batch[ws] : -1;
            for (int n = ws; n < we; n++) {
                int bb = batch[n];
                if (bb != cb) {
                    pool_flush(cb, mx, sm, lane, out);
                    mx = make_float2(NEGMAX, NEGMAX);
                    sm = make_float2(0.f, 0.f);
                    cb = bb;
                }
                if (nt[n] == 1) {
                    const float* basep;
                    if (bl[n] >= 1) {
                        basep = g_bout + (size_t)g_bslot[n] * DD;
                    } else {
                        int fp = g_fslot[n];
                        basep = (fl[n] >= 1)
                            ? g_fout + (size_t)(fp & SLOT_MASK) * DD
                            : g_tab + ((fp >> 20) & 0xF) * DD;
                    }
                    float2 v = *((const float2*)basep + lane);
                    mx.x = fmaxf(mx.x, v.x);
                    mx.y = fmaxf(mx.y, v.y);
                    sm.x += v.x;
                    sm.y += v.y;
                }
            }
            if (cb >= 0) pool_flush(cb, mx, sm, lane, out);
        }
    }
    grid_bar(base + (++nbar));

    // ---- fixup (block 0) ----
    if (blockIdx.x == 0) {
        for (int i = threadIdx.x; i < BBATCH * DD; i += 128) {
            int b = i >> 6, d = i & 63;
            int pos = b * 128 + d;
            unsigned u = __ldcg((const unsigned*)out + pos);
            out[pos] = dec_f(u);
        }
    }
}

// ---------------- PDL launch helper ----------------
template <typename... Args>
static void pdl(void (*kern)(Args...), int grid, int block, Args... args) {
    cudaLaunchConfig_t cfg = {};
    cfg.gridDim = dim3(grid, 1, 1);
    cfg.blockDim = dim3(block, 1, 1);
    cfg.stream = 0;
    cudaLaunchAttribute attr;
    attr.id = cudaLaunchAttributeProgrammaticStreamSerialization;
    attr.val.programmaticStreamSerializationAllowed = 1;
    cfg.attrs = &attr;
    cfg.numAttrs = 1;
    cudaLaunchKernelEx(&cfg, kern, args...);
}

// ---------------- launch ----------------
extern "C" void kernel_launch(void* const* d_in, const int* in_sizes, int n_in,
                              void* d_out, int out_size) {
    const int* nt    = (const int*)d_in[0];
    const int* nip   = (const int*)d_in[1];
    const int* ei    = (const int*)d_in[2];
    const int* fl    = (const int*)d_in[3];
    const int* bl    = (const int*)d_in[4];
    const int* batch = (const int*)d_in[5];
    const float* W_enc = (const float*)d_in[6];
    const float* b_enc = (const float*)d_in[7];
    const float* W_f   = (const float*)d_in[8];
    const float* b_f   = (const float*)d_in[9];
    const float* W_b   = (const float*)d_in[10];
    const float* b_b   = (const float*)d_in[11];
    float* out = (float*)d_out;

    k_zero<<<196, 256>>>(out);
    pdl(k_deg_hist, NB2, 256, ei, fl, bl);
    pdl(k_hscan, 1, 768);
    pdl(k_assign2, NB2, 256, fl, bl, nt, nip);
    pdl(k_scan1, 2 * SCAN_NB, 256);
    pdl(k_scan2p, 1, 256, W_enc, b_enc);
    pdl(k_scan3, 784, 256);
    pdl(k_scatter_e, 1600, 256, ei, fl);
    pdl(k_persist, PGRID, 128, nt, batch, fl, bl, W_f, b_f, W_b, b_b, out);
}